// round 3
// baseline (speedup 1.0000x reference)
#include <cuda_runtime.h>

// ---------------------------------------------------------------------------
// 6-qubit, 3-layer parameterized circuit, B=131072, f32x2-packed simulation.
// One thread = one state: 32 packed-real + 32 packed-imag f32x2 registers;
// pack p holds amplitudes (2p, 2p+1)  [pair dim = qubit 5].
// Per-layer RX*RY*RZ fused into one SU(2) matrix per qubit (prep kernel).
// ---------------------------------------------------------------------------

typedef unsigned long long u64;
#define SGN2 0x8000000080000000ULL

__device__ __forceinline__ u64 pk2(float a, float b) {
    u64 r; asm("mov.b64 %0,{%1,%2};" : "=l"(r) : "f"(a), "f"(b)); return r;
}
__device__ __forceinline__ void upk2(u64 v, float& a, float& b) {
    asm("mov.b64 {%0,%1},%2;" : "=f"(a), "=f"(b) : "l"(v));
}
__device__ __forceinline__ u64 bc2(float a) { return pk2(a, a); }
__device__ __forceinline__ u64 f2mul(u64 a, u64 b) {
    u64 d; asm("mul.rn.f32x2 %0,%1,%2;" : "=l"(d) : "l"(a), "l"(b)); return d;
}
__device__ __forceinline__ u64 f2fma(u64 a, u64 b, u64 c) {
    u64 d; asm("fma.rn.f32x2 %0,%1,%2,%3;" : "=l"(d) : "l"(a), "l"(b), "l"(c)); return d;
}
__device__ __forceinline__ u64 f2add(u64 a, u64 b) {
    u64 d; asm("add.rn.f32x2 %0,%1,%2;" : "=l"(d) : "l"(a), "l"(b)); return d;
}
__device__ __forceinline__ u64 f2swap(u64 a) {
    u64 d;
    asm("{\n\t.reg .b32 x,y;\n\tmov.b64 {x,y},%1;\n\tmov.b64 %0,{y,x};\n\t}"
        : "=l"(d) : "l"(a));
    return d;
}

// Fused per-(l,q) unitary U = Rz*Ry*Rx, 12 u64 slots per gate.
//  q<5 : [r00,i00,n00, r01,i01,n01, r10,i10,n10, r11,i11,n11]  (broadcast pairs)
//  q=5 : [ar=(u00r,u11r), ai, nai, br=(u01r,u10r), bi, nbi]    (first 6 slots)
__device__ u64 g_u[18 * 12];

__global__ void prep_kernel(const float* __restrict__ theta) {
    int t = threadIdx.x;
    if (t < 18) {
        int l = t / 6, q = t % 6;
        const float* th = theta + t * 3;
        float sx, cx, sy, cy, sz, cz;
        __sincosf(th[0] * 0.5f, &sx, &cx);
        __sincosf(th[1] * 0.5f, &sy, &cy);
        float z = th[2] * 0.5f;
        // Last-layer RZ on Z-measured qubits (q even) is unobservable -> drop.
        if (l == 2 && (q % 2 == 0)) z = 0.0f;
        __sincosf(z, &sz, &cz);
        // M = Ry*Rx
        float m00r =  cy * cx, m00i =  sy * sx;
        float m01r = -sy * cx, m01i = -cy * sx;
        float m10r =  sy * cx, m10i = -cy * sx;
        float m11r =  cy * cx, m11i = -sy * sx;
        // U = Rz*M : row0 *= e^{-iz}, row1 *= e^{+iz}
        float u00r = cz * m00r + sz * m00i, u00i = cz * m00i - sz * m00r;
        float u01r = cz * m01r + sz * m01i, u01i = cz * m01i - sz * m01r;
        float u10r = cz * m10r - sz * m10i, u10i = cz * m10i + sz * m10r;
        float u11r = cz * m11r - sz * m11i, u11i = cz * m11i + sz * m11r;
        u64* g = g_u + t * 12;
        if (q < 5) {
            g[0]  = bc2(u00r); g[1]  = bc2(u00i); g[2]  = bc2(-u00i);
            g[3]  = bc2(u01r); g[4]  = bc2(u01i); g[5]  = bc2(-u01i);
            g[6]  = bc2(u10r); g[7]  = bc2(u10i); g[8]  = bc2(-u10i);
            g[9]  = bc2(u11r); g[10] = bc2(u11i); g[11] = bc2(-u11i);
        } else {
            g[0] = pk2(u00r, u11r); g[1] = pk2(u00i, u11i); g[2] = pk2(-u00i, -u11i);
            g[3] = pk2(u01r, u10r); g[4] = pk2(u01i, u10i); g[5] = pk2(-u01i, -u10i);
        }
    }
}

// Fused general 2x2 complex gate on qubit Q (0..4): cross-pack butterflies.
template <int Q>
__device__ __forceinline__ void su2_p(u64* R, u64* I, const u64* __restrict__ u) {
    u64 r00 = u[0], i00 = u[1], n00 = u[2];
    u64 r01 = u[3], i01 = u[4], n01 = u[5];
    u64 r10 = u[6], i10 = u[7], n10 = u[8];
    u64 r11 = u[9], i11 = u[10], n11 = u[11];
    constexpr int Mp = 1 << (4 - Q);
#pragma unroll
    for (int g = 0; g < 16; g++) {
        int p0 = (g & (Mp - 1)) | ((g & ~(Mp - 1)) << 1);
        int p1 = p0 | Mp;
        u64 Ar = R[p0], Ai = I[p0], Br = R[p1], Bi = I[p1];
        // A' = u00*A + u01*B ; B' = u10*A + u11*B   (complex)
        R[p0] = f2fma(n01, Bi, f2fma(r01, Br, f2fma(n00, Ai, f2mul(r00, Ar))));
        I[p0] = f2fma(i01, Br, f2fma(r01, Bi, f2fma(i00, Ar, f2mul(r00, Ai))));
        R[p1] = f2fma(n11, Bi, f2fma(r11, Br, f2fma(n10, Ai, f2mul(r10, Ar))));
        I[p1] = f2fma(i11, Br, f2fma(r11, Bi, f2fma(i10, Ar, f2mul(r10, Ai))));
    }
}

// Fused gate on qubit 5: within-pack butterfly via half-swap.
__device__ __forceinline__ void su2_5p(u64* R, u64* I, const u64* __restrict__ u) {
    u64 ar = u[0], ai = u[1], nai = u[2];
    u64 br = u[3], bi = u[4], nbi = u[5];
#pragma unroll
    for (int p = 0; p < 32; p++) {
        u64 r = R[p], m = I[p];
        u64 sr = f2swap(r), sm = f2swap(m);
        R[p] = f2fma(nbi, sm, f2fma(br, sr, f2fma(nai, m, f2mul(ar, r))));
        I[p] = f2fma(bi, sr, f2fma(br, sm, f2fma(ai, r, f2mul(ar, m))));
    }
}

// ---- CNOTs ----
template <int C, int T>  // C,T in 0..4 -> pure pack permutation (free)
__device__ __forceinline__ void cnot_p(u64* R, u64* I) {
    constexpr int MC = 1 << (5 - C), MTp = 1 << (4 - T);
#pragma unroll
    for (int p = 0; p < 32; p++) {
        if (((2 * p) & MC) && !(p & MTp)) {
            int q = p | MTp;
            u64 t = R[p]; R[p] = R[q]; R[q] = t;
            t = I[p]; I[p] = I[q]; I[q] = t;
        }
    }
}
__device__ __forceinline__ void cnot45_p(u64* R, u64* I) {  // control q4, target q5
#pragma unroll
    for (int p = 1; p < 32; p += 2) {
        R[p] = f2swap(R[p]);
        I[p] = f2swap(I[p]);
    }
}
__device__ __forceinline__ void cnot50_p(u64* R, u64* I) {  // control q5, target q0
#pragma unroll
    for (int p = 0; p < 16; p++) {
        float a0, a1, b0, b1;
        upk2(R[p], a0, a1); upk2(R[p + 16], b0, b1);
        R[p] = pk2(a0, b1); R[p + 16] = pk2(b0, a1);
        upk2(I[p], a0, a1); upk2(I[p + 16], b0, b1);
        I[p] = pk2(a0, b1); I[p + 16] = pk2(b0, a1);
    }
}

__global__ __launch_bounds__(128, 3) void qsim_kernel(
    const float* __restrict__ x, float* __restrict__ out, int Bn)
{
    int b = blockIdx.x * blockDim.x + threadIdx.x;
    if (b >= Bn) return;

    // --- encoding: per-qubit 2-vector after RX(a) RZ(a/2) on |0> ---
    const float4* x4 = reinterpret_cast<const float4*>(x) + (long)b * 6;
    float u0r[6], u0i[6], u1r[6], u1i[6];
#pragma unroll
    for (int q = 0; q < 6; q++) {
        float4 v = __ldg(&x4[q]);
        float a = (v.x + v.y + v.z + v.w) * 0.25f;
        a = fminf(6.0f, fmaxf(-6.0f, a)) * (3.14159265358979323846f / 6.0f);
        float s2, c2, s4, c4;
        __sincosf(a * 0.5f, &s2, &c2);
        __sincosf(a * 0.25f, &s4, &c4);
        u0r[q] = c2 * c4;  u0i[q] = -c2 * s4;
        u1r[q] = s2 * s4;  u1i[q] = -s2 * c4;
    }

    // --- product state, packed: pack dim = qubit 5 first ---
    u64 R[32], I[32];
    R[0] = pk2(u0r[5], u1r[5]);
    I[0] = pk2(u0i[5], u1i[5]);
#pragma unroll
    for (int qq = 1; qq < 6; qq++) {
        int q = 5 - qq;
        int n2 = 1 << (qq - 1);
        u64 a0 = bc2(u0r[q]), b0 = bc2(u0i[q]), nb0 = bc2(-u0i[q]);
        u64 a1 = bc2(u1r[q]), b1 = bc2(u1i[q]), nb1 = bc2(-u1i[q]);
#pragma unroll
        for (int j = 0; j < 16; j++) {
            if (j < n2) {  // constant-folds under full unroll
                u64 tr = R[j], ti = I[j];
                R[j + n2] = f2fma(nb1, ti, f2mul(a1, tr));
                I[j + n2] = f2fma(b1, tr, f2mul(a1, ti));
                R[j]      = f2fma(nb0, ti, f2mul(a0, tr));
                I[j]      = f2fma(b0, tr, f2mul(a0, ti));
            }
        }
    }

    // --- entangling layers: CNOT ring, then one fused SU(2) per qubit ---
#pragma unroll
    for (int l = 0; l < 3; l++) {
        cnot_p<0, 1>(R, I);
        cnot_p<1, 2>(R, I);
        cnot_p<2, 3>(R, I);
        cnot_p<3, 4>(R, I);
        cnot45_p(R, I);
        cnot50_p(R, I);
        const u64* cf = g_u + l * 72;  // 6 gates * 12 slots
        su2_p<0>(R, I, cf + 0);
        su2_p<1>(R, I, cf + 12);
        su2_p<2>(R, I, cf + 24);
        su2_p<3>(R, I, cf + 36);
        su2_p<4>(R, I, cf + 48);
        su2_5p(R, I, cf + 60);
    }

    // --- measurements (packed accumulation) ---
    u64 az0 = 0, az2 = 0, az4 = 0;
    u64 ax1 = 0, ax3 = 0, ax5 = 0;
#pragma unroll
    for (int p = 0; p < 32; p++) {
        u64 pr = f2fma(I[p], I[p], f2mul(R[p], R[p]));
        az0 = f2add(az0, ((2 * p) & 32) ? (pr ^ SGN2) : pr);
        az2 = f2add(az2, ((2 * p) & 8)  ? (pr ^ SGN2) : pr);
        az4 = f2add(az4, ((2 * p) & 2)  ? (pr ^ SGN2) : pr);
        if (!(p & 8)) ax1 = f2fma(R[p], R[p | 8], f2fma(I[p], I[p | 8], ax1));
        if (!(p & 2)) ax3 = f2fma(R[p], R[p | 2], f2fma(I[p], I[p | 2], ax3));
        ax5 = f2fma(R[p], f2swap(R[p]), f2fma(I[p], f2swap(I[p]), ax5));
    }
    float lo, hi;
    upk2(az0, lo, hi); float z0 = lo + hi;
    upk2(az2, lo, hi); float z2 = lo + hi;
    upk2(az4, lo, hi); float z4 = lo + hi;
    upk2(ax1, lo, hi); float x1 = 2.0f * (lo + hi);
    upk2(ax3, lo, hi); float x3 = 2.0f * (lo + hi);
    upk2(ax5, lo, hi); float x5 = 2.0f * lo;  // both halves hold the same sum

    // out row: [Z0, X1, Z2, X3, Z4, X5, Z0, X1]
    float4* o4 = reinterpret_cast<float4*>(out) + (long)b * 2;
    o4[0] = make_float4(z0, x1, z2, x3);
    o4[1] = make_float4(z4, x5, z0, x1);
}

extern "C" void kernel_launch(void* const* d_in, const int* in_sizes, int n_in,
                              void* d_out, int out_size) {
    const float* x     = (const float*)d_in[0];
    const float* theta = (const float*)d_in[1];
    float* out = (float*)d_out;
    int Bn = in_sizes[0] / 24;

    prep_kernel<<<1, 32>>>(theta);
    int blocks = (Bn + 127) / 128;
    qsim_kernel<<<blocks, 128>>>(x, out, Bn);
}

// round 4
// speedup vs baseline: 1.4838x; 1.4838x over previous
#include <cuda_runtime.h>

// ---------------------------------------------------------------------------
// 6-qubit, 3-layer parameterized circuit, B=131072, f32x2-packed simulation.
// One thread = one state: 32 packed-real + 32 packed-imag f32x2 registers;
// pack p holds amplitudes (2p, 2p+1)  [pair dim = qubit 5].
// Per-layer RX*RY*RZ fused into ONE SU(2) gate per qubit: U=[[a,b],[-b*,a*]],
// only 4 real coefficients -> 7 broadcast u64 live (no spills).
// ---------------------------------------------------------------------------

typedef unsigned long long u64;
#define SGN2 0x8000000080000000ULL

__device__ __forceinline__ u64 pk2(float a, float b) {
    u64 r; asm("mov.b64 %0,{%1,%2};" : "=l"(r) : "f"(a), "f"(b)); return r;
}
__device__ __forceinline__ void upk2(u64 v, float& a, float& b) {
    asm("mov.b64 {%0,%1},%2;" : "=f"(a), "=f"(b) : "l"(v));
}
__device__ __forceinline__ u64 bc2(float a) { return pk2(a, a); }
__device__ __forceinline__ u64 f2mul(u64 a, u64 b) {
    u64 d; asm("mul.rn.f32x2 %0,%1,%2;" : "=l"(d) : "l"(a), "l"(b)); return d;
}
__device__ __forceinline__ u64 f2fma(u64 a, u64 b, u64 c) {
    u64 d; asm("fma.rn.f32x2 %0,%1,%2,%3;" : "=l"(d) : "l"(a), "l"(b), "l"(c)); return d;
}
__device__ __forceinline__ u64 f2add(u64 a, u64 b) {
    u64 d; asm("add.rn.f32x2 %0,%1,%2;" : "=l"(d) : "l"(a), "l"(b)); return d;
}
__device__ __forceinline__ u64 f2swap(u64 a) {
    u64 d;
    asm("{\n\t.reg .b32 x,y;\n\tmov.b64 {x,y},%1;\n\tmov.b64 %0,{y,x};\n\t}"
        : "=l"(d) : "l"(a));
    return d;
}

// Fused per-(l,q) SU(2) unitary U = Rz*Ry*Rx, 8 u64 slots per gate.
//  q<5 : [ar, ai, nai, br, nbr, bi, nbi]           (broadcast pairs)
//  q=5 : [aa=(ar,ar), am=(-ai,ai), bp=(br,-br), nb2=(-bi,-bi),
//         ap=(ai,-ai), bb=(bi,bi)]                 (first 6 slots)
__device__ u64 g_u[18 * 8];

__global__ void prep_kernel(const float* __restrict__ theta) {
    int t = threadIdx.x;
    if (t < 18) {
        int l = t / 6, q = t % 6;
        const float* th = theta + t * 3;
        float sx, cx, sy, cy, sz, cz;
        __sincosf(th[0] * 0.5f, &sx, &cx);
        __sincosf(th[1] * 0.5f, &sy, &cy);
        float z = th[2] * 0.5f;
        // Last-applied RZ on Z-measured (even) qubits in last layer commutes
        // with the measurement -> drop exactly.
        if (l == 2 && (q % 2 == 0)) z = 0.0f;
        __sincosf(z, &sz, &cz);
        // M = Ry*Rx ; U = Rz*M is SU(2): a = U00, b = U01.
        float m00r =  cy * cx, m00i =  sy * sx;
        float m01r = -sy * cx, m01i = -cy * sx;
        float ar = cz * m00r + sz * m00i, ai = cz * m00i - sz * m00r;
        float br = cz * m01r + sz * m01i, bi = cz * m01i - sz * m01r;
        u64* g = g_u + t * 8;
        if (q < 5) {
            g[0] = bc2(ar); g[1] = bc2(ai); g[2] = bc2(-ai);
            g[3] = bc2(br); g[4] = bc2(-br); g[5] = bc2(bi); g[6] = bc2(-bi);
        } else {
            g[0] = pk2(ar, ar);   g[1] = pk2(-ai, ai);
            g[2] = pk2(br, -br);  g[3] = pk2(-bi, -bi);
            g[4] = pk2(ai, -ai);  g[5] = pk2(bi, bi);
        }
    }
}

// Fused SU(2) gate on qubit Q (0..4): cross-pack butterflies.
// A' = a*A + b*B ; B' = -b**A + a**B
template <int Q>
__device__ __forceinline__ void su2_p(u64* R, u64* I, const u64* __restrict__ u) {
    u64 ar = u[0], ai = u[1], nai = u[2];
    u64 br = u[3], nbr = u[4], bi = u[5], nbi = u[6];
    constexpr int Mp = 1 << (4 - Q);
#pragma unroll
    for (int g = 0; g < 16; g++) {
        int p0 = (g & (Mp - 1)) | ((g & ~(Mp - 1)) << 1);
        int p1 = p0 | Mp;
        u64 Ar = R[p0], Ai = I[p0], Br = R[p1], Bi = I[p1];
        R[p0] = f2fma(nbi, Bi, f2fma(br, Br, f2fma(nai, Ai, f2mul(ar, Ar))));
        I[p0] = f2fma(br, Bi, f2fma(bi, Br, f2fma(ai, Ar, f2mul(ar, Ai))));
        R[p1] = f2fma(ai, Bi, f2fma(ar, Br, f2fma(nbi, Ai, f2mul(nbr, Ar))));
        I[p1] = f2fma(nai, Br, f2fma(ar, Bi, f2fma(bi, Ar, f2mul(nbr, Ai))));
    }
}

// Fused SU(2) gate on qubit 5: within-pack butterfly via half-swap.
__device__ __forceinline__ void su2_5p(u64* R, u64* I, const u64* __restrict__ u) {
    u64 aa = u[0], am = u[1], bp = u[2], nb2 = u[3], ap = u[4], bb = u[5];
#pragma unroll
    for (int p = 0; p < 32; p++) {
        u64 r = R[p], m = I[p];
        u64 sr = f2swap(r), sm = f2swap(m);
        R[p] = f2fma(nb2, sm, f2fma(bp, sr, f2fma(am, m, f2mul(aa, r))));
        I[p] = f2fma(bb, sr, f2fma(bp, sm, f2fma(ap, r, f2mul(aa, m))));
    }
}

// ---- CNOTs ----
template <int C, int T>  // C,T in 0..4 -> pure pack permutation (free)
__device__ __forceinline__ void cnot_p(u64* R, u64* I) {
    constexpr int MC = 1 << (5 - C), MTp = 1 << (4 - T);
#pragma unroll
    for (int p = 0; p < 32; p++) {
        if (((2 * p) & MC) && !(p & MTp)) {
            int q = p | MTp;
            u64 t = R[p]; R[p] = R[q]; R[q] = t;
            t = I[p]; I[p] = I[q]; I[q] = t;
        }
    }
}
__device__ __forceinline__ void cnot45_p(u64* R, u64* I) {  // control q4, target q5
#pragma unroll
    for (int p = 1; p < 32; p += 2) {
        R[p] = f2swap(R[p]);
        I[p] = f2swap(I[p]);
    }
}
__device__ __forceinline__ void cnot50_p(u64* R, u64* I) {  // control q5, target q0
#pragma unroll
    for (int p = 0; p < 16; p++) {
        float a0, a1, b0, b1;
        upk2(R[p], a0, a1); upk2(R[p + 16], b0, b1);
        R[p] = pk2(a0, b1); R[p + 16] = pk2(b0, a1);
        upk2(I[p], a0, a1); upk2(I[p + 16], b0, b1);
        I[p] = pk2(a0, b1); I[p + 16] = pk2(b0, a1);
    }
}

__global__ __launch_bounds__(128, 3) void qsim_kernel(
    const float* __restrict__ x, float* __restrict__ out, int Bn)
{
    int b = blockIdx.x * blockDim.x + threadIdx.x;
    if (b >= Bn) return;

    // --- encoding: per-qubit 2-vector after RX(a) RZ(a/2) on |0> ---
    const float4* x4 = reinterpret_cast<const float4*>(x) + (long)b * 6;
    float u0r[6], u0i[6], u1r[6], u1i[6];
#pragma unroll
    for (int q = 0; q < 6; q++) {
        float4 v = __ldg(&x4[q]);
        float a = (v.x + v.y + v.z + v.w) * 0.25f;
        a = fminf(6.0f, fmaxf(-6.0f, a)) * (3.14159265358979323846f / 6.0f);
        float s2, c2, s4, c4;
        __sincosf(a * 0.5f, &s2, &c2);
        __sincosf(a * 0.25f, &s4, &c4);
        u0r[q] = c2 * c4;  u0i[q] = -c2 * s4;
        u1r[q] = s2 * s4;  u1i[q] = -s2 * c4;
    }

    // --- product state, packed: pack dim = qubit 5 first ---
    u64 R[32], I[32];
    R[0] = pk2(u0r[5], u1r[5]);
    I[0] = pk2(u0i[5], u1i[5]);
#pragma unroll
    for (int qq = 1; qq < 6; qq++) {
        int q = 5 - qq;
        int n2 = 1 << (qq - 1);
        u64 a0 = bc2(u0r[q]), b0 = bc2(u0i[q]), nb0 = bc2(-u0i[q]);
        u64 a1 = bc2(u1r[q]), b1 = bc2(u1i[q]), nb1 = bc2(-u1i[q]);
#pragma unroll
        for (int j = 0; j < 16; j++) {
            if (j < n2) {  // constant-folds under full unroll
                u64 tr = R[j], ti = I[j];
                R[j + n2] = f2fma(nb1, ti, f2mul(a1, tr));
                I[j + n2] = f2fma(b1, tr, f2mul(a1, ti));
                R[j]      = f2fma(nb0, ti, f2mul(a0, tr));
                I[j]      = f2fma(b0, tr, f2mul(a0, ti));
            }
        }
    }

    // --- entangling layers: CNOT ring, then one fused SU(2) per qubit ---
#pragma unroll
    for (int l = 0; l < 3; l++) {
        cnot_p<0, 1>(R, I);
        cnot_p<1, 2>(R, I);
        cnot_p<2, 3>(R, I);
        cnot_p<3, 4>(R, I);
        cnot45_p(R, I);
        cnot50_p(R, I);
        const u64* cf = g_u + l * 48;  // 6 gates * 8 slots
        su2_p<0>(R, I, cf + 0);
        su2_p<1>(R, I, cf + 8);
        su2_p<2>(R, I, cf + 16);
        su2_p<3>(R, I, cf + 24);
        su2_p<4>(R, I, cf + 32);
        su2_5p(R, I, cf + 40);
    }

    // --- measurements (packed accumulation) ---
    u64 az0 = 0, az2 = 0, az4 = 0;
    u64 ax1 = 0, ax3 = 0, ax5 = 0;
#pragma unroll
    for (int p = 0; p < 32; p++) {
        u64 pr = f2fma(I[p], I[p], f2mul(R[p], R[p]));
        az0 = f2add(az0, ((2 * p) & 32) ? (pr ^ SGN2) : pr);
        az2 = f2add(az2, ((2 * p) & 8)  ? (pr ^ SGN2) : pr);
        az4 = f2add(az4, ((2 * p) & 2)  ? (pr ^ SGN2) : pr);
        if (!(p & 8)) ax1 = f2fma(R[p], R[p | 8], f2fma(I[p], I[p | 8], ax1));
        if (!(p & 2)) ax3 = f2fma(R[p], R[p | 2], f2fma(I[p], I[p | 2], ax3));
        ax5 = f2fma(R[p], f2swap(R[p]), f2fma(I[p], f2swap(I[p]), ax5));
    }
    float lo, hi;
    upk2(az0, lo, hi); float z0 = lo + hi;
    upk2(az2, lo, hi); float z2 = lo + hi;
    upk2(az4, lo, hi); float z4 = lo + hi;
    upk2(ax1, lo, hi); float x1 = 2.0f * (lo + hi);
    upk2(ax3, lo, hi); float x3 = 2.0f * (lo + hi);
    upk2(ax5, lo, hi); float x5 = 2.0f * lo;  // both halves hold the same sum

    // out row: [Z0, X1, Z2, X3, Z4, X5, Z0, X1]
    float4* o4 = reinterpret_cast<float4*>(out) + (long)b * 2;
    o4[0] = make_float4(z0, x1, z2, x3);
    o4[1] = make_float4(z4, x5, z0, x1);
}

extern "C" void kernel_launch(void* const* d_in, const int* in_sizes, int n_in,
                              void* d_out, int out_size) {
    const float* x     = (const float*)d_in[0];
    const float* theta = (const float*)d_in[1];
    float* out = (float*)d_out;
    int Bn = in_sizes[0] / 24;

    prep_kernel<<<1, 32>>>(theta);
    int blocks = (Bn + 127) / 128;
    qsim_kernel<<<blocks, 128>>>(x, out, Bn);
}

// round 5
// speedup vs baseline: 1.4990x; 1.0102x over previous
#include <cuda_runtime.h>

// ---------------------------------------------------------------------------
// 6-qubit, 3-layer parameterized circuit, B=131072, f32x2-packed simulation.
// One thread = one state: 32 packed-real + 32 packed-imag f32x2 registers;
// pack p holds amplitudes (2p, 2p+1)  [pair dim = qubit 5].
// Per-layer RX*RY*RZ fused into ONE SU(2) gate per qubit: U=[[a,b],[-b*,a*]],
// only 4 real coefficients -> 7 broadcast u64 live (no spills).
// ---------------------------------------------------------------------------

typedef unsigned long long u64;
#define SGN2 0x8000000080000000ULL

__device__ __forceinline__ u64 pk2(float a, float b) {
    u64 r; asm("mov.b64 %0,{%1,%2};" : "=l"(r) : "f"(a), "f"(b)); return r;
}
__device__ __forceinline__ void upk2(u64 v, float& a, float& b) {
    asm("mov.b64 {%0,%1},%2;" : "=f"(a), "=f"(b) : "l"(v));
}
__device__ __forceinline__ u64 bc2(float a) { return pk2(a, a); }
__device__ __forceinline__ u64 f2mul(u64 a, u64 b) {
    u64 d; asm("mul.rn.f32x2 %0,%1,%2;" : "=l"(d) : "l"(a), "l"(b)); return d;
}
__device__ __forceinline__ u64 f2fma(u64 a, u64 b, u64 c) {
    u64 d; asm("fma.rn.f32x2 %0,%1,%2,%3;" : "=l"(d) : "l"(a), "l"(b), "l"(c)); return d;
}
__device__ __forceinline__ u64 f2add(u64 a, u64 b) {
    u64 d; asm("add.rn.f32x2 %0,%1,%2;" : "=l"(d) : "l"(a), "l"(b)); return d;
}
__device__ __forceinline__ u64 f2swap(u64 a) {
    u64 d;
    asm("{\n\t.reg .b32 x,y;\n\tmov.b64 {x,y},%1;\n\tmov.b64 %0,{y,x};\n\t}"
        : "=l"(d) : "l"(a));
    return d;
}

// Fused per-(l,q) SU(2) unitary U = Rz*Ry*Rx, 8 u64 slots per gate.
//  q<5 : [ar, ai, nai, br, nbr, bi, nbi]           (broadcast pairs)
//  q=5 : [aa=(ar,ar), am=(-ai,ai), bp=(br,-br), nb2=(-bi,-bi),
//         ap=(ai,-ai), bb=(bi,bi)]                 (first 6 slots)
__device__ u64 g_u[18 * 8];

__global__ void prep_kernel(const float* __restrict__ theta) {
    int t = threadIdx.x;
    if (t < 18) {
        int l = t / 6, q = t % 6;
        const float* th = theta + t * 3;
        float sx, cx, sy, cy, sz, cz;
        __sincosf(th[0] * 0.5f, &sx, &cx);
        __sincosf(th[1] * 0.5f, &sy, &cy);
        float z = th[2] * 0.5f;
        // Last-applied RZ on Z-measured (even) qubits in last layer commutes
        // with the measurement -> drop exactly.
        if (l == 2 && (q % 2 == 0)) z = 0.0f;
        __sincosf(z, &sz, &cz);
        // M = Ry*Rx ; U = Rz*M is SU(2): a = U00, b = U01.
        float m00r =  cy * cx, m00i =  sy * sx;
        float m01r = -sy * cx, m01i = -cy * sx;
        float ar = cz * m00r + sz * m00i, ai = cz * m00i - sz * m00r;
        float br = cz * m01r + sz * m01i, bi = cz * m01i - sz * m01r;
        u64* g = g_u + t * 8;
        if (q < 5) {
            g[0] = bc2(ar); g[1] = bc2(ai); g[2] = bc2(-ai);
            g[3] = bc2(br); g[4] = bc2(-br); g[5] = bc2(bi); g[6] = bc2(-bi);
        } else {
            g[0] = pk2(ar, ar);   g[1] = pk2(-ai, ai);
            g[2] = pk2(br, -br);  g[3] = pk2(-bi, -bi);
            g[4] = pk2(ai, -ai);  g[5] = pk2(bi, bi);
        }
    }
}

// Fused SU(2) gate on qubit Q (0..4): cross-pack butterflies.
// A' = a*A + b*B ; B' = -b**A + a**B
template <int Q>
__device__ __forceinline__ void su2_p(u64* R, u64* I, const u64* __restrict__ u) {
    u64 ar = u[0], ai = u[1], nai = u[2];
    u64 br = u[3], nbr = u[4], bi = u[5], nbi = u[6];
    constexpr int Mp = 1 << (4 - Q);
#pragma unroll
    for (int g = 0; g < 16; g++) {
        int p0 = (g & (Mp - 1)) | ((g & ~(Mp - 1)) << 1);
        int p1 = p0 | Mp;
        u64 Ar = R[p0], Ai = I[p0], Br = R[p1], Bi = I[p1];
        R[p0] = f2fma(nbi, Bi, f2fma(br, Br, f2fma(nai, Ai, f2mul(ar, Ar))));
        I[p0] = f2fma(br, Bi, f2fma(bi, Br, f2fma(ai, Ar, f2mul(ar, Ai))));
        R[p1] = f2fma(ai, Bi, f2fma(ar, Br, f2fma(nbi, Ai, f2mul(nbr, Ar))));
        I[p1] = f2fma(nai, Br, f2fma(ar, Bi, f2fma(bi, Ar, f2mul(nbr, Ai))));
    }
}

// Fused SU(2) gate on qubit 5: within-pack butterfly via half-swap.
__device__ __forceinline__ void su2_5p(u64* R, u64* I, const u64* __restrict__ u) {
    u64 aa = u[0], am = u[1], bp = u[2], nb2 = u[3], ap = u[4], bb = u[5];
#pragma unroll
    for (int p = 0; p < 32; p++) {
        u64 r = R[p], m = I[p];
        u64 sr = f2swap(r), sm = f2swap(m);
        R[p] = f2fma(nb2, sm, f2fma(bp, sr, f2fma(am, m, f2mul(aa, r))));
        I[p] = f2fma(bb, sr, f2fma(bp, sm, f2fma(ap, r, f2mul(aa, m))));
    }
}

// ---- CNOTs ----
template <int C, int T>  // C,T in 0..4 -> pure pack permutation (free)
__device__ __forceinline__ void cnot_p(u64* R, u64* I) {
    constexpr int MC = 1 << (5 - C), MTp = 1 << (4 - T);
#pragma unroll
    for (int p = 0; p < 32; p++) {
        if (((2 * p) & MC) && !(p & MTp)) {
            int q = p | MTp;
            u64 t = R[p]; R[p] = R[q]; R[q] = t;
            t = I[p]; I[p] = I[q]; I[q] = t;
        }
    }
}
__device__ __forceinline__ void cnot45_p(u64* R, u64* I) {  // control q4, target q5
#pragma unroll
    for (int p = 1; p < 32; p += 2) {
        R[p] = f2swap(R[p]);
        I[p] = f2swap(I[p]);
    }
}
__device__ __forceinline__ void cnot50_p(u64* R, u64* I) {  // control q5, target q0
#pragma unroll
    for (int p = 0; p < 16; p++) {
        float a0, a1, b0, b1;
        upk2(R[p], a0, a1); upk2(R[p + 16], b0, b1);
        R[p] = pk2(a0, b1); R[p + 16] = pk2(b0, a1);
        upk2(I[p], a0, a1); upk2(I[p + 16], b0, b1);
        I[p] = pk2(a0, b1); I[p + 16] = pk2(b0, a1);
    }
}

__global__ __launch_bounds__(128, 3) void qsim_kernel(
    const float* __restrict__ x, float* __restrict__ out, int Bn)
{
    int b = blockIdx.x * blockDim.x + threadIdx.x;
    if (b >= Bn) return;

    // --- encoding: per-qubit 2-vector after RX(a) RZ(a/2) on |0> ---
    const float4* x4 = reinterpret_cast<const float4*>(x) + (long)b * 6;
    float u0r[6], u0i[6], u1r[6], u1i[6];
#pragma unroll
    for (int q = 0; q < 6; q++) {
        float4 v = __ldg(&x4[q]);
        float a = (v.x + v.y + v.z + v.w) * 0.25f;
        a = fminf(6.0f, fmaxf(-6.0f, a)) * (3.14159265358979323846f / 6.0f);
        float s2, c2, s4, c4;
        __sincosf(a * 0.5f, &s2, &c2);
        __sincosf(a * 0.25f, &s4, &c4);
        u0r[q] = c2 * c4;  u0i[q] = -c2 * s4;
        u1r[q] = s2 * s4;  u1i[q] = -s2 * c4;
    }

    // --- product state, packed: pack dim = qubit 5 first ---
    u64 R[32], I[32];
    R[0] = pk2(u0r[5], u1r[5]);
    I[0] = pk2(u0i[5], u1i[5]);
#pragma unroll
    for (int qq = 1; qq < 6; qq++) {
        int q = 5 - qq;
        int n2 = 1 << (qq - 1);
        u64 a0 = bc2(u0r[q]), b0 = bc2(u0i[q]), nb0 = bc2(-u0i[q]);
        u64 a1 = bc2(u1r[q]), b1 = bc2(u1i[q]), nb1 = bc2(-u1i[q]);
#pragma unroll
        for (int j = 0; j < 16; j++) {
            if (j < n2) {  // constant-folds under full unroll
                u64 tr = R[j], ti = I[j];
                R[j + n2] = f2fma(nb1, ti, f2mul(a1, tr));
                I[j + n2] = f2fma(b1, tr, f2mul(a1, ti));
                R[j]      = f2fma(nb0, ti, f2mul(a0, tr));
                I[j]      = f2fma(b0, tr, f2mul(a0, ti));
            }
        }
    }

    // --- entangling layers: CNOT ring, then one fused SU(2) per qubit ---
#pragma unroll
    for (int l = 0; l < 3; l++) {
        cnot_p<0, 1>(R, I);
        cnot_p<1, 2>(R, I);
        cnot_p<2, 3>(R, I);
        cnot_p<3, 4>(R, I);
        cnot45_p(R, I);
        cnot50_p(R, I);
        const u64* cf = g_u + l * 48;  // 6 gates * 8 slots
        su2_p<0>(R, I, cf + 0);
        su2_p<1>(R, I, cf + 8);
        su2_p<2>(R, I, cf + 16);
        su2_p<3>(R, I, cf + 24);
        su2_p<4>(R, I, cf + 32);
        su2_5p(R, I, cf + 40);
    }

    // --- measurements (packed accumulation) ---
    u64 az0 = 0, az2 = 0, az4 = 0;
    u64 ax1 = 0, ax3 = 0, ax5 = 0;
#pragma unroll
    for (int p = 0; p < 32; p++) {
        u64 pr = f2fma(I[p], I[p], f2mul(R[p], R[p]));
        az0 = f2add(az0, ((2 * p) & 32) ? (pr ^ SGN2) : pr);
        az2 = f2add(az2, ((2 * p) & 8)  ? (pr ^ SGN2) : pr);
        az4 = f2add(az4, ((2 * p) & 2)  ? (pr ^ SGN2) : pr);
        if (!(p & 8)) ax1 = f2fma(R[p], R[p | 8], f2fma(I[p], I[p | 8], ax1));
        if (!(p & 2)) ax3 = f2fma(R[p], R[p | 2], f2fma(I[p], I[p | 2], ax3));
        ax5 = f2fma(R[p], f2swap(R[p]), f2fma(I[p], f2swap(I[p]), ax5));
    }
    float lo, hi;
    upk2(az0, lo, hi); float z0 = lo + hi;
    upk2(az2, lo, hi); float z2 = lo + hi;
    upk2(az4, lo, hi); float z4 = lo + hi;
    upk2(ax1, lo, hi); float x1 = 2.0f * (lo + hi);
    upk2(ax3, lo, hi); float x3 = 2.0f * (lo + hi);
    upk2(ax5, lo, hi); float x5 = 2.0f * lo;  // both halves hold the same sum

    // out row: [Z0, X1, Z2, X3, Z4, X5, Z0, X1]
    float4* o4 = reinterpret_cast<float4*>(out) + (long)b * 2;
    o4[0] = make_float4(z0, x1, z2, x3);
    o4[1] = make_float4(z4, x5, z0, x1);
}

extern "C" void kernel_launch(void* const* d_in, const int* in_sizes, int n_in,
                              void* d_out, int out_size) {
    const float* x     = (const float*)d_in[0];
    const float* theta = (const float*)d_in[1];
    float* out = (float*)d_out;
    int Bn = in_sizes[0] / 24;

    prep_kernel<<<1, 32>>>(theta);
    int blocks = (Bn + 127) / 128;
    qsim_kernel<<<blocks, 128>>>(x, out, Bn);
}

// round 6
// speedup vs baseline: 1.6354x; 1.0910x over previous
#include <cuda_runtime.h>

// ---------------------------------------------------------------------------
// 6-qubit, 3-layer circuit, B=131072. TWO threads per state (thread bit = q0),
// each holding 16 packed-f32x2 real + 16 imag registers (pack lane = q5 bit,
// pack bits 3..0 = q1..q4). 64 state regs/thread -> 4 warps/SMSP.
// CNOT(4,5) and CNOT(5,0) are folded into the cross-thread q0 gate's gather;
// CNOT(0,1) is a t-conditional pack swap (SELs); other CNOTs are free renames.
// ---------------------------------------------------------------------------

typedef unsigned long long u64;
#define SGN2 0x8000000080000000ULL

__device__ __forceinline__ u64 pk2(float a, float b) {
    u64 r; asm("mov.b64 %0,{%1,%2};" : "=l"(r) : "f"(a), "f"(b)); return r;
}
__device__ __forceinline__ void upk2(u64 v, float& a, float& b) {
    asm("mov.b64 {%0,%1},%2;" : "=f"(a), "=f"(b) : "l"(v));
}
__device__ __forceinline__ u64 bc2(float a) { return pk2(a, a); }
__device__ __forceinline__ u64 f2mul(u64 a, u64 b) {
    u64 d; asm("mul.rn.f32x2 %0,%1,%2;" : "=l"(d) : "l"(a), "l"(b)); return d;
}
__device__ __forceinline__ u64 f2fma(u64 a, u64 b, u64 c) {
    u64 d; asm("fma.rn.f32x2 %0,%1,%2,%3;" : "=l"(d) : "l"(a), "l"(b), "l"(c)); return d;
}
__device__ __forceinline__ u64 f2add(u64 a, u64 b) {
    u64 d; asm("add.rn.f32x2 %0,%1,%2;" : "=l"(d) : "l"(a), "l"(b)); return d;
}
__device__ __forceinline__ u64 f2swap(u64 a) {
    u64 d;
    asm("{\n\t.reg .b32 x,y;\n\tmov.b64 {x,y},%1;\n\tmov.b64 %0,{y,x};\n\t}"
        : "=l"(d) : "l"(a));
    return d;
}

// Fused per-(l,q) SU(2) unitary U = Rz*Ry*Rx, 8 u64 slots per gate.
//  q=0 : [ar, ai, br, bi, nbi]                       (broadcast pairs)
//  1-4 : [ar, ai, nai, br, nbr, bi, nbi]             (broadcast pairs)
//  q=5 : [aa=(ar,ar), am=(-ai,ai), bp=(br,-br), nb2=(-bi,-bi),
//         ap=(ai,-ai), bb=(bi,bi)]
__device__ u64 g_u[18 * 8];

__global__ void prep_kernel(const float* __restrict__ theta) {
    int t = threadIdx.x;
    if (t < 18) {
        int l = t / 6, q = t % 6;
        const float* th = theta + t * 3;
        float sx, cx, sy, cy, sz, cz;
        __sincosf(th[0] * 0.5f, &sx, &cx);
        __sincosf(th[1] * 0.5f, &sy, &cy);
        float z = th[2] * 0.5f;
        // Last-applied RZ on Z-measured (even) qubits, last layer: unobservable.
        if (l == 2 && (q % 2 == 0)) z = 0.0f;
        __sincosf(z, &sz, &cz);
        float m00r =  cy * cx, m00i =  sy * sx;
        float m01r = -sy * cx, m01i = -cy * sx;
        float ar = cz * m00r + sz * m00i, ai = cz * m00i - sz * m00r;
        float br = cz * m01r + sz * m01i, bi = cz * m01i - sz * m01r;
        u64* g = g_u + t * 8;
        if (q == 0) {
            g[0] = bc2(ar); g[1] = bc2(ai); g[2] = bc2(br);
            g[3] = bc2(bi); g[4] = bc2(-bi);
        } else if (q < 5) {
            g[0] = bc2(ar); g[1] = bc2(ai); g[2] = bc2(-ai);
            g[3] = bc2(br); g[4] = bc2(-br); g[5] = bc2(bi); g[6] = bc2(-bi);
        } else {
            g[0] = pk2(ar, ar);   g[1] = pk2(-ai, ai);
            g[2] = pk2(br, -br);  g[3] = pk2(-bi, -bi);
            g[4] = pk2(ai, -ai);  g[5] = pk2(bi, bi);
        }
    }
}

// Local SU(2) on qubit Q in 1..4 (pack bit 4-Q), 16 packs, 8 butterflies.
template <int Q>
__device__ __forceinline__ void su2_loc(u64* R, u64* I, const u64* __restrict__ u) {
    u64 ar = u[0], ai = u[1], nai = u[2];
    u64 br = u[3], nbr = u[4], bi = u[5], nbi = u[6];
    constexpr int Mp = 1 << (4 - Q);
#pragma unroll
    for (int g = 0; g < 8; g++) {
        int p0 = (g & (Mp - 1)) | ((g & ~(Mp - 1)) << 1);
        int p1 = p0 | Mp;
        u64 Ar = R[p0], Ai = I[p0], Br = R[p1], Bi = I[p1];
        R[p0] = f2fma(nbi, Bi, f2fma(br, Br, f2fma(nai, Ai, f2mul(ar, Ar))));
        I[p0] = f2fma(br, Bi, f2fma(bi, Br, f2fma(ai, Ar, f2mul(ar, Ai))));
        R[p1] = f2fma(ai, Bi, f2fma(ar, Br, f2fma(nbi, Ai, f2mul(nbr, Ar))));
        I[p1] = f2fma(nai, Br, f2fma(ar, Bi, f2fma(bi, Ar, f2mul(nbr, Ai))));
    }
}

// Local SU(2) on qubit 5 (lane), within-pack butterfly via half-swap.
__device__ __forceinline__ void su2_q5(u64* R, u64* I, const u64* __restrict__ u) {
    u64 aa = u[0], am = u[1], bp = u[2], nb2 = u[3], ap = u[4], bb = u[5];
#pragma unroll
    for (int p = 0; p < 16; p++) {
        u64 r = R[p], m = I[p];
        u64 sr = f2swap(r), sm = f2swap(m);
        R[p] = f2fma(nb2, sm, f2fma(bp, sr, f2fma(am, m, f2mul(aa, r))));
        I[p] = f2fma(bb, sr, f2fma(bp, sm, f2fma(ap, r, f2mul(aa, m))));
    }
}

__device__ __forceinline__ void swp(u64* A, int i, int j) {
    u64 t = A[i]; A[i] = A[j]; A[j] = t;
}

__global__ __launch_bounds__(128, 4) void qsim_kernel(
    const float* __restrict__ x, float* __restrict__ out, int Bn)
{
    int gid = blockIdx.x * 128 + threadIdx.x;
    int st = gid >> 1;
    if (st >= Bn) return;
    int t = gid & 1;
    u64 smask = t ? SGN2 : 0ULL;

    // --- encoding: per-qubit 2-vector after RX(a) RZ(a/2) on |0> ---
    const float4* x4 = reinterpret_cast<const float4*>(x) + (long)st * 6;
    float u0r[6], u0i[6], u1r[6], u1i[6];
#pragma unroll
    for (int q = 0; q < 6; q++) {
        float4 v = __ldg(&x4[q]);
        float a = (v.x + v.y + v.z + v.w) * 0.25f;
        a = fminf(6.0f, fmaxf(-6.0f, a)) * (3.14159265358979323846f / 6.0f);
        float s2, c2, s4, c4;
        __sincosf(a * 0.5f, &s2, &c2);
        __sincosf(a * 0.25f, &s4, &c4);
        u0r[q] = c2 * c4;  u0i[q] = -c2 * s4;
        u1r[q] = s2 * s4;  u1i[q] = -s2 * c4;
    }

    // --- product state: q0 factor by thread bit, then lane=q5, packs q4..q1 ---
    float cr = t ? u1r[0] : u0r[0];
    float ci = t ? u1i[0] : u0i[0];
    u64 R[16], I[16];
    R[0] = pk2(cr * u0r[5] - ci * u0i[5], cr * u1r[5] - ci * u1i[5]);
    I[0] = pk2(cr * u0i[5] + ci * u0r[5], cr * u1i[5] + ci * u1r[5]);
#pragma unroll
    for (int qq = 1; qq < 5; qq++) {
        int q = 5 - qq;       // 4,3,2,1
        int n2 = 1 << (qq - 1);
        u64 a0 = bc2(u0r[q]), b0 = bc2(u0i[q]), nb0 = bc2(-u0i[q]);
        u64 a1 = bc2(u1r[q]), b1 = bc2(u1i[q]), nb1 = bc2(-u1i[q]);
#pragma unroll
        for (int j = 0; j < 8; j++) {
            if (j < n2) {  // constant-folds under full unroll
                u64 tr = R[j], ti = I[j];
                R[j + n2] = f2fma(nb1, ti, f2mul(a1, tr));
                I[j + n2] = f2fma(b1, tr, f2mul(a1, ti));
                R[j]      = f2fma(nb0, ti, f2mul(a0, tr));
                I[j]      = f2fma(b0, tr, f2mul(a0, ti));
            }
        }
    }

    // --- 3 layers ---
#pragma unroll
    for (int l = 0; l < 3; l++) {
        // CNOT(0,1): control = thread bit -> conditional swap p <-> p|8
#pragma unroll
        for (int p = 0; p < 8; p++) {
            u64 a = R[p], b = R[p + 8];
            R[p] = t ? b : a;  R[p + 8] = t ? a : b;
            a = I[p]; b = I[p + 8];
            I[p] = t ? b : a;  I[p + 8] = t ? a : b;
        }
        // CNOT(1,2): packs with bit3: flip bit2 (free renames)
        swp(R, 8, 12); swp(R, 9, 13); swp(R, 10, 14); swp(R, 11, 15);
        swp(I, 8, 12); swp(I, 9, 13); swp(I, 10, 14); swp(I, 11, 15);
        // CNOT(2,3): packs with bit2: flip bit1
        swp(R, 4, 6); swp(R, 5, 7); swp(R, 12, 14); swp(R, 13, 15);
        swp(I, 4, 6); swp(I, 5, 7); swp(I, 12, 14); swp(I, 13, 15);
        // CNOT(3,4): packs with bit1: flip bit0
        swp(R, 2, 3); swp(R, 6, 7); swp(R, 10, 11); swp(R, 14, 15);
        swp(I, 2, 3); swp(I, 6, 7); swp(I, 10, 11); swp(I, 14, 15);

        const u64* cf = g_u + l * 48;

        // Gate on q0 (cross-thread), with CNOT(4,5) and CNOT(5,0) folded in.
        // thread0 coeffs (a,b); thread1 (a*, -b*): sign via XOR.
        {
            u64 car  = cf[0];
            u64 cai  = cf[1] ^ smask;
            u64 ncai = cai ^ SGN2;
            u64 cbr  = cf[2] ^ smask;
            u64 cbi  = cf[3];
            u64 ncbi = cf[4];
#pragma unroll
            for (int p = 0; p < 16; p++) {
                u64 LR = R[p], LI = I[p];
                u64 MR = __shfl_xor_sync(0xffffffffu, LR, 1);
                u64 MI = __shfl_xor_sync(0xffffffffu, LI, 1);
                float lr0, lr1, li0, li1, mr0, mr1, mi0, mi1;
                upk2(LR, lr0, lr1); upk2(LI, li0, li1);
                upk2(MR, mr0, mr1); upk2(MI, mi0, mi1);
                u64 AR, AI, BR, BI;
                if ((p & 1) == 0) {  // even pack: C45 identity, C50 hi-lane cross
                    AR = pk2(lr0, mr1); AI = pk2(li0, mi1);
                    BR = pk2(mr0, lr1); BI = pk2(mi0, li1);
                } else {             // odd pack: C45 lane-swap then C50
                    AR = pk2(lr1, mr0); AI = pk2(li1, mi0);
                    BR = pk2(mr1, lr0); BI = pk2(mi1, li0);
                }
                R[p] = f2fma(ncbi, BI, f2fma(cbr, BR, f2fma(ncai, AI, f2mul(car, AR))));
                I[p] = f2fma(cbi, BR, f2fma(cbr, BI, f2fma(cai, AR, f2mul(car, AI))));
            }
        }

        su2_loc<1>(R, I, cf + 8);
        su2_loc<2>(R, I, cf + 16);
        su2_loc<3>(R, I, cf + 24);
        su2_loc<4>(R, I, cf + 32);
        su2_q5(R, I, cf + 40);
    }

    // --- measurements (local packed partials) ---
    u64 aS = 0, az2 = 0, az4 = 0, ax1 = 0, ax3 = 0, ax5 = 0;
#pragma unroll
    for (int p = 0; p < 16; p++) {
        u64 pr = f2fma(I[p], I[p], f2mul(R[p], R[p]));
        aS  = f2add(aS, pr);
        az2 = f2add(az2, (p & 4) ? (pr ^ SGN2) : pr);
        az4 = f2add(az4, (p & 1) ? (pr ^ SGN2) : pr);
        if (!(p & 8)) ax1 = f2fma(R[p], R[p | 8], f2fma(I[p], I[p | 8], ax1));
        if (!(p & 2)) ax3 = f2fma(R[p], R[p | 2], f2fma(I[p], I[p | 2], ax3));
        ax5 = f2fma(R[p], f2swap(R[p]), f2fma(I[p], f2swap(I[p]), ax5));
    }
    float lo, hi;
    upk2(aS,  lo, hi); float S   = lo + hi;
    float z0l = t ? -S : S;
    upk2(az2, lo, hi); float z2l = lo + hi;
    upk2(az4, lo, hi); float z4l = lo + hi;
    upk2(ax1, lo, hi); float x1l = lo + hi;
    upk2(ax3, lo, hi); float x3l = lo + hi;
    upk2(ax5, lo, hi); float x5l = lo;       // both lanes hold the same sum

    float z0 = z0l + __shfl_xor_sync(0xffffffffu, z0l, 1);
    float z2 = z2l + __shfl_xor_sync(0xffffffffu, z2l, 1);
    float z4 = z4l + __shfl_xor_sync(0xffffffffu, z4l, 1);
    float x1 = 2.0f * (x1l + __shfl_xor_sync(0xffffffffu, x1l, 1));
    float x3 = 2.0f * (x3l + __shfl_xor_sync(0xffffffffu, x3l, 1));
    float x5 = 2.0f * (x5l + __shfl_xor_sync(0xffffffffu, x5l, 1));

    if (t == 0) {
        float4* o4 = reinterpret_cast<float4*>(out) + (long)st * 2;
        o4[0] = make_float4(z0, x1, z2, x3);
        o4[1] = make_float4(z4, x5, z0, x1);
    }
}

extern "C" void kernel_launch(void* const* d_in, const int* in_sizes, int n_in,
                              void* d_out, int out_size) {
    const float* x     = (const float*)d_in[0];
    const float* theta = (const float*)d_in[1];
    float* out = (float*)d_out;
    int Bn = in_sizes[0] / 24;

    prep_kernel<<<1, 32>>>(theta);
    long threads = 2L * Bn;
    int blocks = (int)((threads + 127) / 128);
    qsim_kernel<<<blocks, 128>>>(x, out, Bn);
}

// round 7
// speedup vs baseline: 1.7006x; 1.0398x over previous
#include <cuda_runtime.h>

// ---------------------------------------------------------------------------
// 6-qubit, 3-layer circuit, B=131072. FOUR threads per state (t1=q0, t0=q1),
// each holding 8 packed-f32x2 real + 8 imag regs (lane = q5; pack bits
// 2..0 = q2,q3,q4). CNOT(0,1) handled as a zero-cost thread-bit relabeling
// that alternates per layer (template<int S>); CNOT(4,5)+(5,0) folded into
// the cross-thread q0 gate gather; CNOT(1,2) = thread-predicated SELs;
// CNOT(2,3),(3,4) = free register renames.
// ---------------------------------------------------------------------------

typedef unsigned long long u64;
#define SGN2 0x8000000080000000ULL

__device__ __forceinline__ u64 pk2(float a, float b) {
    u64 r; asm("mov.b64 %0,{%1,%2};" : "=l"(r) : "f"(a), "f"(b)); return r;
}
__device__ __forceinline__ void upk2(u64 v, float& a, float& b) {
    asm("mov.b64 {%0,%1},%2;" : "=f"(a), "=f"(b) : "l"(v));
}
__device__ __forceinline__ u64 bc2(float a) { return pk2(a, a); }
__device__ __forceinline__ u64 f2mul(u64 a, u64 b) {
    u64 d; asm("mul.rn.f32x2 %0,%1,%2;" : "=l"(d) : "l"(a), "l"(b)); return d;
}
__device__ __forceinline__ u64 f2fma(u64 a, u64 b, u64 c) {
    u64 d; asm("fma.rn.f32x2 %0,%1,%2,%3;" : "=l"(d) : "l"(a), "l"(b), "l"(c)); return d;
}
__device__ __forceinline__ u64 f2add(u64 a, u64 b) {
    u64 d; asm("add.rn.f32x2 %0,%1,%2;" : "=l"(d) : "l"(a), "l"(b)); return d;
}
__device__ __forceinline__ u64 f2swap(u64 a) {
    u64 d;
    asm("{\n\t.reg .b32 x,y;\n\tmov.b64 {x,y},%1;\n\tmov.b64 %0,{y,x};\n\t}"
        : "=l"(d) : "l"(a));
    return d;
}

// Fused per-(l,q) SU(2) unitary U = Rz*Ry*Rx.  48 u64 slots per layer:
//  q0 : [0..4]   ar, ai, br, bi, -bi          (broadcast pairs)
//  q1 : [8..11]  ar, ai, br, bi               (broadcast pairs)
//  q2 : [16..22] ar, ai, -ai, br, -br, bi, -bi
//  q3 : [24..30] same
//  q4 : [32..38] same
//  q5 : [40..45] (ar,ar),(-ai,ai),(br,-br),(-bi,-bi),(ai,-ai),(bi,bi)
__device__ u64 g_u[3 * 48];

__global__ void prep_kernel(const float* __restrict__ theta) {
    int t = threadIdx.x;
    if (t < 18) {
        int l = t / 6, q = t % 6;
        const float* th = theta + t * 3;
        float sx, cx, sy, cy, sz, cz;
        __sincosf(th[0] * 0.5f, &sx, &cx);
        __sincosf(th[1] * 0.5f, &sy, &cy);
        float z = th[2] * 0.5f;
        // Last-applied RZ on Z-measured (even) qubits, last layer: unobservable.
        if (l == 2 && (q % 2 == 0)) z = 0.0f;
        __sincosf(z, &sz, &cz);
        float m00r =  cy * cx, m00i =  sy * sx;
        float m01r = -sy * cx, m01i = -cy * sx;
        float ar = cz * m00r + sz * m00i, ai = cz * m00i - sz * m00r;
        float br = cz * m01r + sz * m01i, bi = cz * m01i - sz * m01r;
        u64* g = g_u + l * 48;
        if (q == 0) {
            g[0] = bc2(ar); g[1] = bc2(ai); g[2] = bc2(br);
            g[3] = bc2(bi); g[4] = bc2(-bi);
        } else if (q == 1) {
            g[8] = bc2(ar); g[9] = bc2(ai); g[10] = bc2(br); g[11] = bc2(bi);
        } else if (q < 5) {
            u64* h = g + 16 + (q - 2) * 8;
            h[0] = bc2(ar); h[1] = bc2(ai); h[2] = bc2(-ai);
            h[3] = bc2(br); h[4] = bc2(-br); h[5] = bc2(bi); h[6] = bc2(-bi);
        } else {
            u64* h = g + 40;
            h[0] = pk2(ar, ar);   h[1] = pk2(-ai, ai);
            h[2] = pk2(br, -br);  h[3] = pk2(-bi, -bi);
            h[4] = pk2(ai, -ai);  h[5] = pk2(bi, bi);
        }
    }
}

// Local SU(2) on a pack bit (MP = 4 -> q2, 2 -> q3, 1 -> q4).
template <int MP>
__device__ __forceinline__ void su2_loc(u64* R, u64* I, const u64* __restrict__ u) {
    u64 ar = u[0], ai = u[1], nai = u[2];
    u64 br = u[3], nbr = u[4], bi = u[5], nbi = u[6];
#pragma unroll
    for (int g = 0; g < 4; g++) {
        int p0 = (g & (MP - 1)) | ((g & ~(MP - 1)) << 1);
        int p1 = p0 | MP;
        u64 Ar = R[p0], Ai = I[p0], Br = R[p1], Bi = I[p1];
        R[p0] = f2fma(nbi, Bi, f2fma(br, Br, f2fma(nai, Ai, f2mul(ar, Ar))));
        I[p0] = f2fma(br, Bi, f2fma(bi, Br, f2fma(ai, Ar, f2mul(ar, Ai))));
        R[p1] = f2fma(ai, Bi, f2fma(ar, Br, f2fma(nbi, Ai, f2mul(nbr, Ar))));
        I[p1] = f2fma(nai, Br, f2fma(ar, Bi, f2fma(bi, Ar, f2mul(nbr, Ai))));
    }
}

// Local SU(2) on qubit 5 (lane), within-pack butterfly via half-swap.
__device__ __forceinline__ void su2_q5(u64* R, u64* I, const u64* __restrict__ u) {
    u64 aa = u[0], am = u[1], bp = u[2], nb2 = u[3], ap = u[4], bb = u[5];
#pragma unroll
    for (int p = 0; p < 8; p++) {
        u64 r = R[p], m = I[p];
        u64 sr = f2swap(r), sm = f2swap(m);
        R[p] = f2fma(nb2, sm, f2fma(bp, sr, f2fma(am, m, f2mul(aa, r))));
        I[p] = f2fma(bb, sr, f2fma(bp, sm, f2fma(ap, r, f2mul(aa, m))));
    }
}

__device__ __forceinline__ void swp(u64* A, int i, int j) {
    u64 t = A[i]; A[i] = A[j]; A[j] = t;
}

// One layer. S = thread-bit mapping AFTER this layer's CNOT(0,1) relabel:
//   S=1: q0=t1, q1=t0^t1 ; S=0: q0=t1, q1=t0.
template <int S>
__device__ __forceinline__ void layer(u64* R, u64* I, const u64* __restrict__ cf,
                                      int t0, int t1) {
    int q1log = S ? (t0 ^ t1) : t0;
    // CNOT(1,2): threads with q1log==1 flip pack bit2.
    bool c = (q1log != 0);
#pragma unroll
    for (int p = 0; p < 4; p++) {
        u64 a = R[p], b = R[p + 4];
        R[p] = c ? b : a;  R[p + 4] = c ? a : b;
        a = I[p]; b = I[p + 4];
        I[p] = c ? b : a;  I[p + 4] = c ? a : b;
    }
    // CNOT(2,3): packs with bit2=1 flip bit1 (free renames)
    swp(R, 4, 6); swp(R, 5, 7); swp(I, 4, 6); swp(I, 5, 7);
    // CNOT(3,4): packs with bit1=1 flip bit0
    swp(R, 2, 3); swp(R, 6, 7); swp(I, 2, 3); swp(I, 6, 7);

    // q0 gate (cross-thread), CNOT(4,5) + CNOT(5,0) folded into the gather.
    // Partner flips logical q0 keeping q1log: xor 3 (S=1) / xor 2 (S=0).
    {
        u64 smask = t1 ? SGN2 : 0ULL;
        u64 car  = cf[0];
        u64 cai  = cf[1] ^ smask;
        u64 ncai = cai ^ SGN2;
        u64 cbr  = cf[2] ^ smask;
        u64 cbi  = cf[3];
        u64 ncbi = cf[4];
        constexpr int PX = S ? 3 : 2;
#pragma unroll
        for (int p = 0; p < 8; p++) {
            u64 LR = R[p], LI = I[p];
            u64 MR = __shfl_xor_sync(0xffffffffu, LR, PX);
            u64 MI = __shfl_xor_sync(0xffffffffu, LI, PX);
            float lr0, lr1, li0, li1, mr0, mr1, mi0, mi1;
            upk2(LR, lr0, lr1); upk2(LI, li0, li1);
            upk2(MR, mr0, mr1); upk2(MI, mi0, mi1);
            u64 AR, AI, BR, BI;
            if ((p & 1) == 0) {  // q4=0: C45 identity, C50 hi-lane cross
                AR = pk2(lr0, mr1); AI = pk2(li0, mi1);
                BR = pk2(mr0, lr1); BI = pk2(mi0, li1);
            } else {             // q4=1: C45 lane-swap then C50
                AR = pk2(lr1, mr0); AI = pk2(li1, mi0);
                BR = pk2(mr1, lr0); BI = pk2(mi1, li0);
            }
            R[p] = f2fma(ncbi, BI, f2fma(cbr, BR, f2fma(ncai, AI, f2mul(car, AR))));
            I[p] = f2fma(cbi, BR, f2fma(cbr, BI, f2fma(cai, AR, f2mul(car, AI))));
        }
    }

    // q1 gate (cross-thread, partner xor 1, role = q1log):
    //   r=0: new = a*L + b*M ;  r=1: new = a**L - b**M
    {
        u64 m1   = q1log ? SGN2 : 0ULL;
        u64 ar   = cf[8];
        u64 cai  = cf[9] ^ m1;
        u64 ncai = cai ^ SGN2;
        u64 cbr  = cf[10] ^ m1;
        u64 bi   = cf[11];
        u64 nbi  = bi ^ SGN2;
#pragma unroll
        for (int p = 0; p < 8; p++) {
            u64 LR = R[p], LI = I[p];
            u64 MR = __shfl_xor_sync(0xffffffffu, LR, 1);
            u64 MI = __shfl_xor_sync(0xffffffffu, LI, 1);
            R[p] = f2fma(nbi, MI, f2fma(cbr, MR, f2fma(ncai, LI, f2mul(ar, LR))));
            I[p] = f2fma(bi, MR, f2fma(cbr, MI, f2fma(cai, LR, f2mul(ar, LI))));
        }
    }

    su2_loc<4>(R, I, cf + 16);  // q2 (pack bit2)
    su2_loc<2>(R, I, cf + 24);  // q3 (pack bit1)
    su2_loc<1>(R, I, cf + 32);  // q4 (pack bit0)
    su2_q5(R, I, cf + 40);      // q5 (lane)
}

__global__ __launch_bounds__(128, 5) void qsim_kernel(
    const float* __restrict__ x, float* __restrict__ out, int Bn)
{
    int gid = blockIdx.x * 128 + threadIdx.x;
    int st = gid >> 2;
    if (st >= Bn) return;
    int t = gid & 3;
    int t0 = t & 1, t1 = (t >> 1) & 1;

    // --- encoding: per-qubit 2-vector after RX(a) RZ(a/2) on |0> ---
    const float4* x4 = reinterpret_cast<const float4*>(x) + (long)st * 6;
    float u0r[6], u0i[6], u1r[6], u1i[6];
#pragma unroll
    for (int q = 0; q < 6; q++) {
        float4 v = __ldg(&x4[q]);
        float a = (v.x + v.y + v.z + v.w) * 0.25f;
        a = fminf(6.0f, fmaxf(-6.0f, a)) * (3.14159265358979323846f / 6.0f);
        float s2, c2, s4, c4;
        __sincosf(a * 0.5f, &s2, &c2);
        __sincosf(a * 0.25f, &s4, &c4);
        u0r[q] = c2 * c4;  u0i[q] = -c2 * s4;
        u1r[q] = s2 * s4;  u1i[q] = -s2 * c4;
    }

    // --- product state: scalar factor for (q0=t1, q1=t0), then lane=q5,
    //     then double packs over q4 (bit0), q3 (bit1), q2 (bit2) ---
    float ar0 = t1 ? u1r[0] : u0r[0],  ai0 = t1 ? u1i[0] : u0i[0];
    float ar1 = t0 ? u1r[1] : u0r[1],  ai1 = t0 ? u1i[1] : u0i[1];
    float cr = ar0 * ar1 - ai0 * ai1;
    float ci = ar0 * ai1 + ai0 * ar1;
    u64 R[8], I[8];
    R[0] = pk2(cr * u0r[5] - ci * u0i[5], cr * u1r[5] - ci * u1i[5]);
    I[0] = pk2(cr * u0i[5] + ci * u0r[5], cr * u1i[5] + ci * u1r[5]);
#pragma unroll
    for (int qq = 0; qq < 3; qq++) {
        int q = 4 - qq;       // 4,3,2
        int n2 = 1 << qq;     // 1,2,4
        u64 a0 = bc2(u0r[q]), b0 = bc2(u0i[q]), nb0 = bc2(-u0i[q]);
        u64 a1 = bc2(u1r[q]), b1 = bc2(u1i[q]), nb1 = bc2(-u1i[q]);
#pragma unroll
        for (int j = 0; j < 4; j++) {
            if (j < n2) {  // constant-folds under full unroll
                u64 tr = R[j], ti = I[j];
                R[j + n2] = f2fma(nb1, ti, f2mul(a1, tr));
                I[j + n2] = f2fma(b1, tr, f2mul(a1, ti));
                R[j]      = f2fma(nb0, ti, f2mul(a0, tr));
                I[j]      = f2fma(b0, tr, f2mul(a0, ti));
            }
        }
    }

    // --- 3 layers; CNOT(0,1) relabel parity alternates 1,0,1 ---
    layer<1>(R, I, g_u + 0,  t0, t1);
    layer<0>(R, I, g_u + 48, t0, t1);
    layer<1>(R, I, g_u + 96, t0, t1);

    // --- measurements (final mapping: q0=t1, q1=t0^t1) ---
    u64 aS = 0, az2 = 0, az4 = 0, ax1 = 0, ax3 = 0, ax5 = 0;
#pragma unroll
    for (int p = 0; p < 8; p++) {
        u64 pr = f2fma(I[p], I[p], f2mul(R[p], R[p]));
        aS  = f2add(aS, pr);
        az2 = f2add(az2, (p & 4) ? (pr ^ SGN2) : pr);
        az4 = f2add(az4, (p & 1) ? (pr ^ SGN2) : pr);
        if (!(p & 2)) ax3 = f2fma(R[p], R[p | 2], f2fma(I[p], I[p | 2], ax3));
        ax5 = f2fma(R[p], f2swap(R[p]), f2fma(I[p], f2swap(I[p]), ax5));
        u64 PR = __shfl_xor_sync(0xffffffffu, R[p], 1);
        u64 PI = __shfl_xor_sync(0xffffffffu, I[p], 1);
        ax1 = f2fma(R[p], PR, f2fma(I[p], PI, ax1));
    }
    float lo, hi;
    upk2(aS,  lo, hi); float S0 = lo + hi;
    float z0 = t1 ? -S0 : S0;
    upk2(az2, lo, hi); float z2 = lo + hi;
    upk2(az4, lo, hi); float z4 = lo + hi;
    upk2(ax1, lo, hi); float x1 = lo + hi;   // pairs double-counted = the 2x
    upk2(ax3, lo, hi); float x3 = lo + hi;
    upk2(ax5, lo, hi); float x5 = lo;        // both lanes hold the same sum

    // reduce across the 4-thread group
    z0 += __shfl_xor_sync(0xffffffffu, z0, 1); z0 += __shfl_xor_sync(0xffffffffu, z0, 2);
    z2 += __shfl_xor_sync(0xffffffffu, z2, 1); z2 += __shfl_xor_sync(0xffffffffu, z2, 2);
    z4 += __shfl_xor_sync(0xffffffffu, z4, 1); z4 += __shfl_xor_sync(0xffffffffu, z4, 2);
    x1 += __shfl_xor_sync(0xffffffffu, x1, 1); x1 += __shfl_xor_sync(0xffffffffu, x1, 2);
    x3 += __shfl_xor_sync(0xffffffffu, x3, 1); x3 += __shfl_xor_sync(0xffffffffu, x3, 2);
    x5 += __shfl_xor_sync(0xffffffffu, x5, 1); x5 += __shfl_xor_sync(0xffffffffu, x5, 2);
    x3 *= 2.0f; x5 *= 2.0f;

    if (t == 0) {
        float4* o4 = reinterpret_cast<float4*>(out) + (long)st * 2;
        o4[0] = make_float4(z0, x1, z2, x3);
        o4[1] = make_float4(z4, x5, z0, x1);
    }
}

extern "C" void kernel_launch(void* const* d_in, const int* in_sizes, int n_in,
                              void* d_out, int out_size) {
    const float* x     = (const float*)d_in[0];
    const float* theta = (const float*)d_in[1];
    float* out = (float*)d_out;
    int Bn = in_sizes[0] / 24;

    prep_kernel<<<1, 32>>>(theta);
    long threads = 4L * Bn;
    int blocks = (int)((threads + 127) / 128);
    qsim_kernel<<<blocks, 128>>>(x, out, Bn);
}